// round 3
// baseline (speedup 1.0000x reference)
#include <cuda_runtime.h>
#include <cstdint>

#define N_NODES 100000
#define N_EDGES 1600000
#define NGRAPH  512
#define D0 64
#define D1 128

// ---------------- scratch (device globals; no allocation allowed) ----------------
__device__ __align__(16) float g_deg[N_NODES];
__device__ __align__(16) float g_h0[N_NODES * D0];       // 25.6 MB
__device__ __align__(16) float g_agg1[N_NODES * D0];     // 25.6 MB
__device__ __align__(16) float g_h1[N_NODES * D1];       // 51.2 MB
__device__ __align__(16) float g_p[N_NODES * D0];        // 25.6 MB  (h1 @ W2l, pre-aggregation)
__device__ __align__(16) float g_agg2[N_NODES * D0];     // 25.6 MB
__device__ unsigned g_omax[NGRAPH * D0];                 // ordered-uint max accumulator

// ordered-uint mapping: monotone in float value
__device__ __forceinline__ unsigned ordf(float f) {
    unsigned u = __float_as_uint(f);
    return (u & 0x80000000u) ? ~u : (u | 0x80000000u);
}
// ordf(-FLT_MAX) == 0x00800000
#define ORD_NEG_INIT 0x00800000u

// ---------------- init: zero deg/agg1/agg2, init omax ----------------
__global__ void init_kernel() {
    int i = blockIdx.x * blockDim.x + threadIdx.x;
    int stride = gridDim.x * blockDim.x;
    const int NA4 = N_NODES * D0 / 4;  // 1.6M float4 per agg
    float4 z = make_float4(0.f, 0.f, 0.f, 0.f);
    for (int j = i; j < NA4; j += stride) {
        ((float4*)g_agg1)[j] = z;
        ((float4*)g_agg2)[j] = z;
    }
    for (int j = i; j < N_NODES; j += stride) g_deg[j] = 0.f;
    for (int j = i; j < NGRAPH * D0; j += stride) g_omax[j] = ORD_NEG_INIT;
}

// ---------------- degree ----------------
__global__ void deg_kernel(const int* __restrict__ dst) {
    int e = blockIdx.x * blockDim.x + threadIdx.x;
    if (e < N_EDGES) atomicAdd(&g_deg[dst[e]], 1.0f);
}

// ---------------- h0 = embed[x] ----------------
__global__ void embed_kernel(const int* __restrict__ x, const float* __restrict__ embed) {
    int i = blockIdx.x * blockDim.x + threadIdx.x;   // N_NODES*16 items (float4 chunks)
    if (i >= N_NODES * 16) return;
    int n = i >> 4, c = i & 15;
    ((float4*)g_h0)[n * 16 + c] = ((const float4*)embed)[(size_t)x[n] * 16 + c];
}

// ---------------- edge scatter (64-wide): agg[dst] += vals[src] ----------------
__global__ void scatter64_kernel(const int* __restrict__ src, const int* __restrict__ dst,
                                 const float* __restrict__ vals, float* __restrict__ agg) {
    unsigned i = blockIdx.x * 256u + threadIdx.x;     // E*16 items
    if (i >= (unsigned)N_EDGES * 16u) return;
    unsigned e = i >> 4, c = i & 15;
    int s = __ldg(src + e);
    int d = __ldg(dst + e);
    float4 v = ((const float4*)vals)[(size_t)s * 16 + c];
    atomicAdd(((float4*)agg) + (size_t)d * 16 + c, v);   // RED.128 through L2
}

// ---------------- dense1: h1 = relu((agg1/deg)@W1l + b1 + h0@W1r)  [64 -> 128] ----------------
// Block: 256 thr (8 warps), 64 nodes/block. SMEM: Wl(32K)+Wr(32K)+AH packed (32K) = 96KB.
// AH packing: float2 (a,h) per (node,k); pairs of nodes interleaved so a single LDS.128
// broadcast fetches 2 nodes' (a,h) at one k.  index(t,k) = (t>>1)*128 + 2k + (t&1)
__global__ void __launch_bounds__(256, 1) dense1_kernel(const float* __restrict__ W1l,
                                                        const float* __restrict__ W1r,
                                                        const float* __restrict__ b1) {
    extern __shared__ float sm[];
    float*  sWl = sm;                       // 8192 floats
    float*  sWr = sm + 8192;                // 8192 floats
    float2* sAH = (float2*)(sm + 16384);    // 4096 float2
    const int tid = threadIdx.x;
    const int n0 = blockIdx.x * 64;

    for (int j = tid; j < 2048; j += 256) {
        ((float4*)sWl)[j] = ((const float4*)W1l)[j];
        ((float4*)sWr)[j] = ((const float4*)W1r)[j];
    }
    for (int idx = tid; idx < 4096; idx += 256) {
        int t = idx >> 6, k = idx & 63;
        int n = n0 + t;
        float a = 0.f, h = 0.f;
        if (n < N_NODES) {
            float invd = 1.0f / fmaxf(g_deg[n], 1.0f);
            a = g_agg1[n * 64 + k] * invd;
            h = g_h0[n * 64 + k];
        }
        sAH[((t >> 1) << 7) + (k << 1) + (t & 1)] = make_float2(a, h);
    }
    __syncthreads();

    const int warp = tid >> 5, lane = tid & 31;
    const int nb = warp * 8;                      // this warp's 8 nodes
    float acc[8][4];
#pragma unroll
    for (int n = 0; n < 8; n++)
#pragma unroll
        for (int c = 0; c < 4; c++) acc[n][c] = 0.f;

    const float4* sWl4 = (const float4*)sWl;
    const float4* sWr4 = (const float4*)sWr;
    const float4* sAH4 = (const float4*)sAH;      // float4 idx = (t>>1)*64 + k -> {a0,h0,a1,h1}
    const int gbase = (nb >> 1) * 64;

#pragma unroll 4
    for (int k = 0; k < 64; k++) {
        float4 wl = sWl4[k * 32 + lane];
        float4 wr = sWr4[k * 32 + lane];
        float wlv[4] = {wl.x, wl.y, wl.z, wl.w};
        float wrv[4] = {wr.x, wr.y, wr.z, wr.w};
#pragma unroll
        for (int p = 0; p < 4; p++) {
            float4 ah = sAH4[gbase + p * 64 + k];
#pragma unroll
            for (int c = 0; c < 4; c++) {
                acc[2 * p][c]     = fmaf(ah.x, wlv[c], acc[2 * p][c]);
                acc[2 * p][c]     = fmaf(ah.y, wrv[c], acc[2 * p][c]);
                acc[2 * p + 1][c] = fmaf(ah.z, wlv[c], acc[2 * p + 1][c]);
                acc[2 * p + 1][c] = fmaf(ah.w, wrv[c], acc[2 * p + 1][c]);
            }
        }
    }

    float4 bb = ((const float4*)b1)[lane];
    float bv[4] = {bb.x, bb.y, bb.z, bb.w};
#pragma unroll
    for (int n = 0; n < 8; n++) {
        int node = n0 + nb + n;
        if (node < N_NODES) {
            float4 o;
            o.x = fmaxf(acc[n][0] + bv[0], 0.f);
            o.y = fmaxf(acc[n][1] + bv[1], 0.f);
            o.z = fmaxf(acc[n][2] + bv[2], 0.f);
            o.w = fmaxf(acc[n][3] + bv[3], 0.f);
            ((float4*)g_h1)[node * 32 + lane] = o;
        }
    }
}

// ---------------- dense_p: p = h1 @ W2l  [128 -> 64] ----------------
// Block: 256 thr, 128 nodes/block. SMEM: W(32K) + H packed (64K) = 96KB.
// H packing: 4 nodes interleaved per k: index(t,k) = (t>>2)*512 + 4k + (t&3)
__global__ void __launch_bounds__(256, 1) dense_p_kernel(const float* __restrict__ W2l) {
    extern __shared__ float sm[];
    float* sW = sm;           // 8192 floats
    float* sH = sm + 8192;    // 16384 floats
    const int tid = threadIdx.x;
    const int n0 = blockIdx.x * 128;

    for (int j = tid; j < 2048; j += 256)
        ((float4*)sW)[j] = ((const float4*)W2l)[j];
    for (int idx = tid; idx < 16384; idx += 256) {
        int t = idx >> 7, k = idx & 127;
        int n = n0 + t;
        float v = (n < N_NODES) ? g_h1[n * 128 + k] : 0.f;
        sH[((t >> 2) << 9) + (k << 2) + (t & 3)] = v;
    }
    __syncthreads();

    const int warp = tid >> 5, lane = tid & 31;
    const int nb = warp * 16;                     // 16 nodes per warp
    float acc[16][2];
#pragma unroll
    for (int n = 0; n < 16; n++) { acc[n][0] = 0.f; acc[n][1] = 0.f; }

    const float2* sW2 = (const float2*)sW;        // cols = lane*2
    const float4* sH4 = (const float4*)sH;        // float4 idx = (t>>2)*128 + k -> 4 nodes @ k

#pragma unroll 2
    for (int k = 0; k < 128; k++) {
        float2 w = sW2[k * 32 + lane];
#pragma unroll
        for (int q = 0; q < 4; q++) {
            float4 hh = sH4[((nb >> 2) + q) * 128 + k];
            float hv[4] = {hh.x, hh.y, hh.z, hh.w};
#pragma unroll
            for (int r = 0; r < 4; r++) {
                acc[q * 4 + r][0] = fmaf(hv[r], w.x, acc[q * 4 + r][0]);
                acc[q * 4 + r][1] = fmaf(hv[r], w.y, acc[q * 4 + r][1]);
            }
        }
    }
#pragma unroll
    for (int n = 0; n < 16; n++) {
        int node = n0 + nb + n;
        if (node < N_NODES)
            ((float2*)g_p)[node * 32 + lane] = make_float2(acc[n][0], acc[n][1]);
    }
}

// ---------------- dense2 + pooled max: h2 = agg2/deg + b2 + h1@W2r ; omax[batch] = max ----------------
__global__ void __launch_bounds__(256, 1) dense2_kernel(const float* __restrict__ W2r,
                                                        const float* __restrict__ b2,
                                                        const int* __restrict__ batch) {
    extern __shared__ float sm[];
    float* sW = sm;
    float* sH = sm + 8192;
    const int tid = threadIdx.x;
    const int n0 = blockIdx.x * 128;

    for (int j = tid; j < 2048; j += 256)
        ((float4*)sW)[j] = ((const float4*)W2r)[j];
    for (int idx = tid; idx < 16384; idx += 256) {
        int t = idx >> 7, k = idx & 127;
        int n = n0 + t;
        float v = (n < N_NODES) ? g_h1[n * 128 + k] : 0.f;
        sH[((t >> 2) << 9) + (k << 2) + (t & 3)] = v;
    }
    __syncthreads();

    const int warp = tid >> 5, lane = tid & 31;
    const int nb = warp * 16;
    float acc[16][2];
#pragma unroll
    for (int n = 0; n < 16; n++) { acc[n][0] = 0.f; acc[n][1] = 0.f; }

    const float2* sW2 = (const float2*)sW;
    const float4* sH4 = (const float4*)sH;

#pragma unroll 2
    for (int k = 0; k < 128; k++) {
        float2 w = sW2[k * 32 + lane];
#pragma unroll
        for (int q = 0; q < 4; q++) {
            float4 hh = sH4[((nb >> 2) + q) * 128 + k];
            float hv[4] = {hh.x, hh.y, hh.z, hh.w};
#pragma unroll
            for (int r = 0; r < 4; r++) {
                acc[q * 4 + r][0] = fmaf(hv[r], w.x, acc[q * 4 + r][0]);
                acc[q * 4 + r][1] = fmaf(hv[r], w.y, acc[q * 4 + r][1]);
            }
        }
    }

    float2 bb = ((const float2*)b2)[lane];
    int curb = -1;
    float mx = 0.f, my = 0.f;
#pragma unroll
    for (int t = 0; t < 16; t++) {
        int node = n0 + nb + t;
        if (node >= N_NODES) break;
        float invd = 1.0f / fmaxf(g_deg[node], 1.0f);
        float2 ag = ((const float2*)g_agg2)[node * 32 + lane];
        float vx = acc[t][0] + ag.x * invd + bb.x;
        float vy = acc[t][1] + ag.y * invd + bb.y;
        int b = batch[node];
        if (b != curb) {
            if (curb >= 0) {
                atomicMax(&g_omax[curb * 64 + lane * 2], ordf(mx));
                atomicMax(&g_omax[curb * 64 + lane * 2 + 1], ordf(my));
            }
            curb = b; mx = vx; my = vy;
        } else {
            mx = fmaxf(mx, vx);
            my = fmaxf(my, vy);
        }
    }
    if (curb >= 0) {
        atomicMax(&g_omax[curb * 64 + lane * 2], ordf(mx));
        atomicMax(&g_omax[curb * 64 + lane * 2 + 1], ordf(my));
    }
}

// ---------------- final: decode ordered uints into d_out ----------------
__global__ void out_kernel(float* __restrict__ out) {
    int i = blockIdx.x * blockDim.x + threadIdx.x;
    if (i >= NGRAPH * D0) return;
    unsigned o = g_omax[i];
    out[i] = (o & 0x80000000u) ? __uint_as_float(o & 0x7FFFFFFFu)
                               : __uint_as_float(~o);
}

// ---------------- launch ----------------
extern "C" void kernel_launch(void* const* d_in, const int* in_sizes, int n_in,
                              void* d_out, int out_size) {
    const int*   x    = (const int*)d_in[0];
    const int*   ei   = (const int*)d_in[1];     // [2, E]
    const int*   batch= (const int*)d_in[2];
    // d_in[3] = edge_attr (unused by SAGEConv)
    const float* embed= (const float*)d_in[4];
    const float* W1l  = (const float*)d_in[5];
    const float* b1   = (const float*)d_in[6];
    const float* W1r  = (const float*)d_in[7];
    const float* W2l  = (const float*)d_in[8];
    const float* b2   = (const float*)d_in[9];
    const float* W2r  = (const float*)d_in[10];
    float* out = (float*)d_out;

    const int* src = ei;
    const int* dst = ei + N_EDGES;

    cudaFuncSetAttribute(dense1_kernel,  cudaFuncAttributeMaxDynamicSharedMemorySize, 98304);
    cudaFuncSetAttribute(dense_p_kernel, cudaFuncAttributeMaxDynamicSharedMemorySize, 98304);
    cudaFuncSetAttribute(dense2_kernel,  cudaFuncAttributeMaxDynamicSharedMemorySize, 98304);

    float* agg1p; cudaGetSymbolAddress((void**)&agg1p, g_agg1);
    float* agg2p; cudaGetSymbolAddress((void**)&agg2p, g_agg2);
    float* h0p;   cudaGetSymbolAddress((void**)&h0p,   g_h0);
    float* pp;    cudaGetSymbolAddress((void**)&pp,    g_p);

    init_kernel<<<2048, 256>>>();
    deg_kernel<<<(N_EDGES + 255) / 256, 256>>>(dst);
    embed_kernel<<<(N_NODES * 16 + 255) / 256, 256>>>(x, embed);
    scatter64_kernel<<<(N_EDGES * 16 + 255) / 256, 256>>>(src, dst, h0p, agg1p);
    dense1_kernel<<<(N_NODES + 63) / 64, 256, 98304>>>(W1l, W1r, b1);
    dense_p_kernel<<<(N_NODES + 127) / 128, 256, 98304>>>(W2l);
    scatter64_kernel<<<(N_EDGES * 16 + 255) / 256, 256>>>(src, dst, pp, agg2p);
    dense2_kernel<<<(N_NODES + 127) / 128, 256, 98304>>>(W2r, b2, batch);
    out_kernel<<<(NGRAPH * D0 + 255) / 256, 256>>>(out);
}

// round 4
// speedup vs baseline: 1.0826x; 1.0826x over previous
#include <cuda_runtime.h>
#include <cstdint>

#define N_NODES 100000
#define N_EDGES 1600000
#define NGRAPH  512
#define D0 64
#define D1 128
#define SCAN_NB 391   // ceil(N_NODES / 256)

// ---------------- scratch (device globals) ----------------
__device__ int g_cnt[N_NODES];
__device__ int g_rowptr[N_NODES + 1];
__device__ int g_cur[N_NODES];
__device__ int g_bsum[SCAN_NB];
__device__ int g_boff[SCAN_NB];
__device__ int g_nbr[N_EDGES];

__device__ __align__(16) float g_agg1[N_NODES * D0];   // meaned neighbor embed
__device__ __align__(16) float g_p[N_NODES * D0];      // h1 @ W2l (pre-aggregation)
__device__ __align__(16) float g_r[N_NODES * D0];      // h1 @ W2r
__device__ __align__(16) float g_agg2[N_NODES * D0];   // meaned neighbor p
__device__ unsigned g_omax[NGRAPH * D0];

// ordered-uint mapping: monotone in float value
__device__ __forceinline__ unsigned ordf(float f) {
    unsigned u = __float_as_uint(f);
    return (u & 0x80000000u) ? ~u : (u | 0x80000000u);
}
#define ORD_NEG_INIT 0x00800000u   // ordf(-FLT_MAX)

// ---------------- f32x2 packed math ----------------
__device__ __forceinline__ unsigned long long pk2(float x, float y) {
    unsigned long long r;
    asm("mov.b64 %0, {%1, %2};" : "=l"(r) : "f"(x), "f"(y));
    return r;
}
__device__ __forceinline__ float2 upk2(unsigned long long v) {
    float2 r;
    asm("mov.b64 {%0, %1}, %2;" : "=f"(r.x), "=f"(r.y) : "l"(v));
    return r;
}
__device__ __forceinline__ void ffma2(unsigned long long& d, unsigned long long a,
                                      unsigned long long b) {
    asm("fma.rn.f32x2 %0, %1, %2, %0;" : "+l"(d) : "l"(a), "l"(b));
}

// ---------------- init: zero counters, init omax ----------------
__global__ void init_kernel() {
    int i = blockIdx.x * 256 + threadIdx.x;
    int stride = gridDim.x * 256;
    for (int j = i; j < N_NODES; j += stride) g_cnt[j] = 0;
    for (int j = i; j < NGRAPH * D0; j += stride) g_omax[j] = ORD_NEG_INIT;
}

// ---------------- histogram of dst ----------------
__global__ void hist_kernel(const int* __restrict__ dst) {
    int e = blockIdx.x * 256 + threadIdx.x;
    if (e < N_EDGES) atomicAdd(&g_cnt[dst[e]], 1);
}

// ---------------- scan step 1: per-256-block sums ----------------
__global__ void scan1_kernel() {
    int b = blockIdx.x;
    int i = b * 256 + threadIdx.x;
    int v = (i < N_NODES) ? g_cnt[i] : 0;
#pragma unroll
    for (int o = 16; o; o >>= 1) v += __shfl_down_sync(0xFFFFFFFFu, v, o);
    __shared__ int ws[8];
    if ((threadIdx.x & 31) == 0) ws[threadIdx.x >> 5] = v;
    __syncthreads();
    if (threadIdx.x == 0) {
        int s = 0;
#pragma unroll
        for (int k = 0; k < 8; k++) s += ws[k];
        g_bsum[b] = s;
    }
}

// ---------------- scan step 2: exclusive scan of block sums (1 block) ----------------
__global__ void scan2_kernel() {
    __shared__ int s[512];
    int t = threadIdx.x;
    int v = (t < SCAN_NB) ? g_bsum[t] : 0;
    s[t] = v;
    __syncthreads();
    for (int o = 1; o < 512; o <<= 1) {
        int u = (t >= o) ? s[t - o] : 0;
        __syncthreads();
        s[t] += u;
        __syncthreads();
    }
    if (t < SCAN_NB) g_boff[t] = s[t] - v;
    if (t == 0) g_rowptr[N_NODES] = N_EDGES;
}

// ---------------- scan step 3: in-block exclusive scan + offset -> rowptr, cur ----------------
__global__ void scan3_kernel() {
    int b = blockIdx.x, t = threadIdx.x;
    int i = b * 256 + t;
    int v = (i < N_NODES) ? g_cnt[i] : 0;
    int lane = t & 31, w = t >> 5;
    int sc = v;
#pragma unroll
    for (int o = 1; o < 32; o <<= 1) {
        int u = __shfl_up_sync(0xFFFFFFFFu, sc, o);
        if (lane >= o) sc += u;
    }
    __shared__ int ws[8];
    if (lane == 31) ws[w] = sc;
    __syncthreads();
    if (t < 8) {
        int u = ws[t];
        int s2 = u;
#pragma unroll
        for (int o = 1; o < 8; o <<= 1) {
            int q = __shfl_up_sync(0xFFu, s2, o);
            if (t >= o) s2 += q;
        }
        ws[t] = s2 - u;   // exclusive warp offset
    }
    __syncthreads();
    int excl = sc - v + ws[w] + g_boff[b];
    if (i < N_NODES) {
        g_rowptr[i] = excl;
        g_cur[i] = excl;
    }
}

// ---------------- fill neighbor lists ----------------
__global__ void fill_kernel(const int* __restrict__ src, const int* __restrict__ dst) {
    int e = blockIdx.x * 256 + threadIdx.x;
    if (e >= N_EDGES) return;
    int d = dst[e];
    int pos = atomicAdd(&g_cur[d], 1);
    g_nbr[pos] = src[e];
}

// ---------------- gather1: agg1[n] = mean_{s in N(n)} embed[x[s]] ----------------
__global__ void gather1_kernel(const int* __restrict__ x, const float* __restrict__ embed) {
    int gt = blockIdx.x * 256 + threadIdx.x;
    int n = gt >> 5;
    if (n >= N_NODES) return;
    int lane = gt & 31;
    int beg = __ldg(g_rowptr + n), end = __ldg(g_rowptr + n + 1);
    const float2* e2 = (const float2*)embed;
    float ax = 0.f, ay = 0.f;
    int j = beg;
    for (; j + 1 < end; j += 2) {
        int s0 = __ldg(g_nbr + j), s1 = __ldg(g_nbr + j + 1);
        int x0 = __ldg(x + s0), x1 = __ldg(x + s1);
        float2 v0 = e2[(size_t)x0 * 32 + lane];
        float2 v1 = e2[(size_t)x1 * 32 + lane];
        ax += v0.x + v1.x;
        ay += v0.y + v1.y;
    }
    if (j < end) {
        int s0 = __ldg(g_nbr + j);
        int x0 = __ldg(x + s0);
        float2 v0 = e2[(size_t)x0 * 32 + lane];
        ax += v0.x;
        ay += v0.y;
    }
    float inv = 1.0f / fmaxf((float)(end - beg), 1.0f);
    ((float2*)g_agg1)[n * 32 + lane] = make_float2(ax * inv, ay * inv);
}

// ---------------- gather2: agg2[n] = mean_{s in N(n)} p[s] ----------------
__global__ void gather2_kernel() {
    int gt = blockIdx.x * 256 + threadIdx.x;
    int n = gt >> 5;
    if (n >= N_NODES) return;
    int lane = gt & 31;
    int beg = __ldg(g_rowptr + n), end = __ldg(g_rowptr + n + 1);
    const float2* p2 = (const float2*)g_p;
    float ax = 0.f, ay = 0.f;
    int j = beg;
    for (; j + 1 < end; j += 2) {
        int s0 = __ldg(g_nbr + j), s1 = __ldg(g_nbr + j + 1);
        float2 v0 = p2[(size_t)s0 * 32 + lane];
        float2 v1 = p2[(size_t)s1 * 32 + lane];
        ax += v0.x + v1.x;
        ay += v0.y + v1.y;
    }
    if (j < end) {
        int s0 = __ldg(g_nbr + j);
        float2 v0 = p2[(size_t)s0 * 32 + lane];
        ax += v0.x;
        ay += v0.y;
    }
    float inv = 1.0f / fmaxf((float)(end - beg), 1.0f);
    ((float2*)g_agg2)[n * 32 + lane] = make_float2(ax * inv, ay * inv);
}

// ---------------- fused dense: h1 = relu(agg1@W1l + b1 + h0@W1r); p = h1@W2l; r = h1@W2r ----
// 256 threads, 64 nodes/block. SMEM 96KB in three 32KB regions, repacked by k-pairs for f32x2.
// Phase1: R0=W1l (packed), R1=W1r, R2=A(16K)+H(16K). Phase2: R0=W2l, R1=W2r, R2=h1 tile.
// Thread covers cols c = lane + 32*cc (conflict-free float2 W reads) for warp's 8 nodes.
__global__ void __launch_bounds__(256, 2) fused_dense_kernel(
    const int* __restrict__ x, const float* __restrict__ embed,
    const float* __restrict__ W1l, const float* __restrict__ W1r,
    const float* __restrict__ b1,
    const float* __restrict__ W2l, const float* __restrict__ W2r)
{
    extern __shared__ float sm[];
    const int tid = threadIdx.x, lane = tid & 31, warp = tid >> 5;
    const int n0 = blockIdx.x * 64;
    const int nb = warp * 8;

    float b1v[4];
#pragma unroll
    for (int cc = 0; cc < 4; cc++) b1v[cc] = __ldg(b1 + lane + 32 * cc);

    // --- stage phase-1 weights, packed: sm[(k>>1)*256 + c*2 + (k&1)] = W[k][c], c in [0,128)
    for (int idx = tid; idx < 8192; idx += 256) {
        int k = idx >> 7, c = idx & 127;
        int d = ((k >> 1) << 8) + (c << 1) + (k & 1);
        sm[d] = W1l[idx];
        sm[8192 + d] = W1r[idx];
    }
    // --- stage A (agg1) and H (embed[x]) tiles, node-pair + k-pair packed:
    // pos = (t>>1)*128 + (k>>1)*4 + (t&1)*2 + (k&1)
    for (int idx = tid; idx < 4096; idx += 256) {
        int t = idx >> 6, k = idx & 63;
        int n = n0 + t;
        float a = 0.f, h = 0.f;
        if (n < N_NODES) {
            a = g_agg1[n * 64 + k];
            int xn = __ldg(x + n);
            h = __ldg(embed + (size_t)xn * 64 + k);
        }
        int pos = ((t >> 1) << 7) + ((k >> 1) << 2) + ((t & 1) << 1) + (k & 1);
        sm[16384 + pos] = a;
        sm[20480 + pos] = h;
    }
    __syncthreads();

    // --- phase 1: h1[t][c] over k=0..63 (32 k-pairs) ---
    unsigned long long acc[8][4];
#pragma unroll
    for (int nn = 0; nn < 8; nn++)
#pragma unroll
        for (int cc = 0; cc < 4; cc++) acc[nn][cc] = 0ull;

    const float2* sWl2 = (const float2*)sm;                // idx j*128 + c
    const float2* sWr2 = (const float2*)(sm + 8192);
    const float4* sA4 = (const float4*)(sm + 16384);       // idx pair*32 + j
    const float4* sH4 = (const float4*)(sm + 20480);

    for (int j = 0; j < 32; j++) {
        unsigned long long wl[4], wr[4];
#pragma unroll
        for (int cc = 0; cc < 4; cc++) {
            float2 t1 = sWl2[j * 128 + lane + 32 * cc];
            float2 t2 = sWr2[j * 128 + lane + 32 * cc];
            wl[cc] = pk2(t1.x, t1.y);
            wr[cc] = pk2(t2.x, t2.y);
        }
#pragma unroll
        for (int p = 0; p < 4; p++) {
            float4 av = sA4[((nb >> 1) + p) * 32 + j];     // broadcast
            float4 hv = sH4[((nb >> 1) + p) * 32 + j];
            unsigned long long a0 = pk2(av.x, av.y), a1 = pk2(av.z, av.w);
            unsigned long long h0 = pk2(hv.x, hv.y), h1 = pk2(hv.z, hv.w);
#pragma unroll
            for (int cc = 0; cc < 4; cc++) {
                ffma2(acc[2 * p][cc], a0, wl[cc]);
                ffma2(acc[2 * p][cc], h0, wr[cc]);
                ffma2(acc[2 * p + 1][cc], a1, wl[cc]);
                ffma2(acc[2 * p + 1][cc], h1, wr[cc]);
            }
        }
    }
    __syncthreads();   // all phase-1 SMEM reads done

    // --- epilogue 1: h1 = relu(lo+hi+b1) -> region2, packed for phase 2:
    // pos = (t>>1)*256 + (c>>1)*4 + (t&1)*2 + (c&1), c in [0,128)
#pragma unroll
    for (int nn = 0; nn < 8; nn++) {
        int t = nb + nn;
#pragma unroll
        for (int cc = 0; cc < 4; cc++) {
            int c = lane + 32 * cc;
            float2 u = upk2(acc[nn][cc]);
            float v = fmaxf(u.x + u.y + b1v[cc], 0.f);
            int pos = ((t >> 1) << 8) + ((c >> 1) << 2) + ((t & 1) << 1) + (c & 1);
            sm[16384 + pos] = v;
        }
    }
    // --- stage phase-2 weights: sm[(k>>1)*128 + c*2 + (k&1)] = W2[k][c], c in [0,64)
    for (int idx = tid; idx < 8192; idx += 256) {
        int k = idx >> 6, c = idx & 63;
        int d = ((k >> 1) << 7) + (c << 1) + (k & 1);
        sm[d] = W2l[idx];
        sm[8192 + d] = W2r[idx];
    }
    __syncthreads();

    // --- phase 2: p, r over k=0..127 (64 k-pairs) ---
    unsigned long long ap[8][2], ar[8][2];
#pragma unroll
    for (int nn = 0; nn < 8; nn++)
#pragma unroll
        for (int cc = 0; cc < 2; cc++) { ap[nn][cc] = 0ull; ar[nn][cc] = 0ull; }

    const float2* sW2l2 = (const float2*)sm;               // idx j2*64 + c
    const float2* sW2r2 = (const float2*)(sm + 8192);
    const float4* sH14 = (const float4*)(sm + 16384);      // idx pair*64 + j2

    for (int j2 = 0; j2 < 64; j2++) {
        unsigned long long w2l[2], w2r[2];
#pragma unroll
        for (int cc = 0; cc < 2; cc++) {
            float2 t1 = sW2l2[j2 * 64 + lane + 32 * cc];
            float2 t2 = sW2r2[j2 * 64 + lane + 32 * cc];
            w2l[cc] = pk2(t1.x, t1.y);
            w2r[cc] = pk2(t2.x, t2.y);
        }
#pragma unroll
        for (int p = 0; p < 4; p++) {
            float4 hv = sH14[((nb >> 1) + p) * 64 + j2];   // broadcast
            unsigned long long h0 = pk2(hv.x, hv.y), h1 = pk2(hv.z, hv.w);
#pragma unroll
            for (int cc = 0; cc < 2; cc++) {
                ffma2(ap[2 * p][cc], h0, w2l[cc]);
                ffma2(ar[2 * p][cc], h0, w2r[cc]);
                ffma2(ap[2 * p + 1][cc], h1, w2l[cc]);
                ffma2(ar[2 * p + 1][cc], h1, w2r[cc]);
            }
        }
    }

    // --- epilogue 2: coalesced scalar stores ---
#pragma unroll
    for (int nn = 0; nn < 8; nn++) {
        int node = n0 + nb + nn;
        if (node < N_NODES) {
#pragma unroll
            for (int cc = 0; cc < 2; cc++) {
                int c = lane + 32 * cc;
                float2 up = upk2(ap[nn][cc]);
                float2 ur = upk2(ar[nn][cc]);
                g_p[node * 64 + c] = up.x + up.y;
                g_r[node * 64 + c] = ur.x + ur.y;
            }
        }
    }
}

// ---------------- final: h2 = agg2 + b2 + r ; run-length segment-max into omax -------------
__global__ void __launch_bounds__(256) final_kernel(const float* __restrict__ b2,
                                                    const int* __restrict__ batch) {
    const int tid = threadIdx.x, lane = tid & 31, warp = tid >> 5;
    const int n0 = blockIdx.x * 128 + warp * 16;
    float2 bb = ((const float2*)b2)[lane];
    const float2* ag2 = (const float2*)g_agg2;
    const float2* r2 = (const float2*)g_r;

    int curb = -1;
    float mx = 0.f, my = 0.f;
#pragma unroll
    for (int t = 0; t < 16; t++) {
        int node = n0 + t;
        if (node >= N_NODES) break;
        float2 ag = ag2[node * 32 + lane];
        float2 rr = r2[node * 32 + lane];
        float vx = ag.x + rr.x + bb.x;
        float vy = ag.y + rr.y + bb.y;
        int b = batch[node];
        if (b != curb) {
            if (curb >= 0) {
                atomicMax(&g_omax[curb * 64 + lane * 2], ordf(mx));
                atomicMax(&g_omax[curb * 64 + lane * 2 + 1], ordf(my));
            }
            curb = b; mx = vx; my = vy;
        } else {
            mx = fmaxf(mx, vx);
            my = fmaxf(my, vy);
        }
    }
    if (curb >= 0) {
        atomicMax(&g_omax[curb * 64 + lane * 2], ordf(mx));
        atomicMax(&g_omax[curb * 64 + lane * 2 + 1], ordf(my));
    }
}

// ---------------- decode ordered uints into d_out ----------------
__global__ void out_kernel(float* __restrict__ out) {
    int i = blockIdx.x * 256 + threadIdx.x;
    if (i >= NGRAPH * D0) return;
    unsigned o = g_omax[i];
    out[i] = (o & 0x80000000u) ? __uint_as_float(o & 0x7FFFFFFFu)
                               : __uint_as_float(~o);
}

// ---------------- launch ----------------
extern "C" void kernel_launch(void* const* d_in, const int* in_sizes, int n_in,
                              void* d_out, int out_size) {
    const int*   x     = (const int*)d_in[0];
    const int*   ei    = (const int*)d_in[1];     // [2, E]
    const int*   batch = (const int*)d_in[2];
    // d_in[3] = edge_attr (unused by SAGEConv)
    const float* embed = (const float*)d_in[4];
    const float* W1l   = (const float*)d_in[5];
    const float* b1    = (const float*)d_in[6];
    const float* W1r   = (const float*)d_in[7];
    const float* W2l   = (const float*)d_in[8];
    const float* b2    = (const float*)d_in[9];
    const float* W2r   = (const float*)d_in[10];
    float* out = (float*)d_out;

    const int* src = ei;
    const int* dst = ei + N_EDGES;

    cudaFuncSetAttribute(fused_dense_kernel,
                         cudaFuncAttributeMaxDynamicSharedMemorySize, 98304);

    init_kernel<<<128, 256>>>();
    hist_kernel<<<(N_EDGES + 255) / 256, 256>>>(dst);
    scan1_kernel<<<SCAN_NB, 256>>>();
    scan2_kernel<<<1, 512>>>();
    scan3_kernel<<<SCAN_NB, 256>>>();
    fill_kernel<<<(N_EDGES + 255) / 256, 256>>>(src, dst);
    gather1_kernel<<<(N_NODES * 32 + 255) / 256, 256>>>(x, embed);
    fused_dense_kernel<<<(N_NODES + 63) / 64, 256, 98304>>>(x, embed, W1l, W1r, b1, W2l, W2r);
    gather2_kernel<<<(N_NODES * 32 + 255) / 256, 256>>>();
    final_kernel<<<(N_NODES + 127) / 128, 256>>>(b2, batch);
    out_kernel<<<(NGRAPH * D0 + 255) / 256, 256>>>(out);
}

// round 6
// speedup vs baseline: 1.6830x; 1.5546x over previous
#include <cuda_runtime.h>
#include <cuda_fp16.h>
#include <cstdint>

#define N_NODES 100000
#define N_EDGES 1600000
#define NGRAPH  512
#define VOCAB   10000
#define D0 64
#define D1 128
#define SCAN_NB 391   // ceil(N_NODES / 256)

// ---------------- scratch (device globals) ----------------
__device__ int g_cnt[N_NODES];
__device__ int g_rowptr[N_NODES + 1];
__device__ int g_cur[N_NODES];
__device__ int g_bsum[SCAN_NB];
__device__ int g_boff[SCAN_NB];
__device__ int g_nbr[N_EDGES];      // src node id per CSR slot (for gather2)
__device__ int g_nbrx[N_EDGES];     // x[src] per CSR slot (for gather1)

__device__ __align__(16) __half g_q[VOCAB * D1];     // embed @ W1l   (fp16, 2.56MB)
__device__ __align__(16) float  g_R[VOCAB * D1];     // embed @ W1r   (fp32, 5.12MB)
__device__ __align__(16) float  g_h1[N_NODES * D1];  // relu layer1   (51.2MB)
__device__ __align__(16) __half g_p[N_NODES * D0];   // h1 @ W2l      (fp16, 12.8MB)
__device__ __align__(16) float  g_r[N_NODES * D0];   // h1 @ W2r      (25.6MB)
__device__ __align__(16) float  g_agg2[N_NODES * D0];
__device__ unsigned g_omax[NGRAPH * D0];

// ordered-uint mapping: monotone in float value
__device__ __forceinline__ unsigned ordf(float f) {
    unsigned u = __float_as_uint(f);
    return (u & 0x80000000u) ? ~u : (u | 0x80000000u);
}
#define ORD_NEG_INIT 0x00800000u   // ordf(-FLT_MAX)

// ---------------- f32x2 packed math ----------------
__device__ __forceinline__ unsigned long long pk2(float x, float y) {
    unsigned long long r;
    asm("mov.b64 %0, {%1, %2};" : "=l"(r) : "f"(x), "f"(y));
    return r;
}
__device__ __forceinline__ float2 upk2(unsigned long long v) {
    float2 r;
    asm("mov.b64 {%0, %1}, %2;" : "=f"(r.x), "=f"(r.y) : "l"(v));
    return r;
}
__device__ __forceinline__ void ffma2(unsigned long long& d, unsigned long long a,
                                      unsigned long long b) {
    asm("fma.rn.f32x2 %0, %1, %2, %0;" : "+l"(d) : "l"(a), "l"(b));
}

// ---------------- init: zero counters, init omax ----------------
__global__ void init_kernel() {
    int i = blockIdx.x * 256 + threadIdx.x;
    int stride = gridDim.x * 256;
    for (int j = i; j < N_NODES; j += stride) g_cnt[j] = 0;
    for (int j = i; j < NGRAPH * D0; j += stride) g_omax[j] = ORD_NEG_INIT;
}

// ---------------- pre: Q = embed@W1l (fp16), R = embed@W1r (fp32) ----------------
// thread per (vocab row v, output col c); warp spans 32 consecutive c of one v
// -> embed loads broadcast, weight loads coalesced; everything L1/L2-hot.
__global__ void pre_kernel(const float* __restrict__ embed,
                           const float* __restrict__ W1l,
                           const float* __restrict__ W1r) {
    int gid = blockIdx.x * 256 + threadIdx.x;
    if (gid >= VOCAB * D1) return;
    int v = gid >> 7, c = gid & 127;
    float q = 0.f, r = 0.f;
#pragma unroll 8
    for (int k = 0; k < 64; k++) {
        float e = __ldg(embed + v * 64 + k);
        q = fmaf(e, __ldg(W1l + k * 128 + c), q);
        r = fmaf(e, __ldg(W1r + k * 128 + c), r);
    }
    g_q[gid] = __float2half_rn(q);
    g_R[gid] = r;
}

// ---------------- histogram of dst ----------------
__global__ void hist_kernel(const int* __restrict__ dst) {
    int e = blockIdx.x * 256 + threadIdx.x;
    if (e < N_EDGES) atomicAdd(&g_cnt[dst[e]], 1);
}

// ---------------- scan step 1 ----------------
__global__ void scan1_kernel() {
    int b = blockIdx.x;
    int i = b * 256 + threadIdx.x;
    int v = (i < N_NODES) ? g_cnt[i] : 0;
#pragma unroll
    for (int o = 16; o; o >>= 1) v += __shfl_down_sync(0xFFFFFFFFu, v, o);
    __shared__ int ws[8];
    if ((threadIdx.x & 31) == 0) ws[threadIdx.x >> 5] = v;
    __syncthreads();
    if (threadIdx.x == 0) {
        int s = 0;
#pragma unroll
        for (int k = 0; k < 8; k++) s += ws[k];
        g_bsum[b] = s;
    }
}

// ---------------- scan step 2 ----------------
__global__ void scan2_kernel() {
    __shared__ int s[512];
    int t = threadIdx.x;
    int v = (t < SCAN_NB) ? g_bsum[t] : 0;
    s[t] = v;
    __syncthreads();
    for (int o = 1; o < 512; o <<= 1) {
        int u = (t >= o) ? s[t - o] : 0;
        __syncthreads();
        s[t] += u;
        __syncthreads();
    }
    if (t < SCAN_NB) g_boff[t] = s[t] - v;
    if (t == 0) g_rowptr[N_NODES] = N_EDGES;
}

// ---------------- scan step 3 ----------------
__global__ void scan3_kernel() {
    int b = blockIdx.x, t = threadIdx.x;
    int i = b * 256 + t;
    int v = (i < N_NODES) ? g_cnt[i] : 0;
    int lane = t & 31, w = t >> 5;
    int sc = v;
#pragma unroll
    for (int o = 1; o < 32; o <<= 1) {
        int u = __shfl_up_sync(0xFFFFFFFFu, sc, o);
        if (lane >= o) sc += u;
    }
    __shared__ int ws[8];
    if (lane == 31) ws[w] = sc;
    __syncthreads();
    if (t < 8) {
        int u = ws[t];
        int s2 = u;
#pragma unroll
        for (int o = 1; o < 8; o <<= 1) {
            int q = __shfl_up_sync(0xFFu, s2, o);
            if (t >= o) s2 += q;
        }
        ws[t] = s2 - u;
    }
    __syncthreads();
    int excl = sc - v + ws[w] + g_boff[b];
    if (i < N_NODES) {
        g_rowptr[i] = excl;
        g_cur[i] = excl;
    }
}

// ---------------- fill neighbor lists (also cache x[src] per slot) ----------------
__global__ void fill_kernel(const int* __restrict__ src, const int* __restrict__ dst,
                            const int* __restrict__ x) {
    int e = blockIdx.x * 256 + threadIdx.x;
    if (e >= N_EDGES) return;
    int d = dst[e];
    int s = src[e];
    int pos = atomicAdd(&g_cur[d], 1);
    g_nbr[pos] = s;
    g_nbrx[pos] = __ldg(x + s);
}

// ---------------- gather1h: h1[n] = relu(mean Q[x[s]] + R[x[n]] + b1) --------------
// warp per node; lane covers 4 cols (uint2 = 4 halves). 4-edge unroll for MLP.
__global__ void __launch_bounds__(256) gather1h_kernel(const int* __restrict__ x,
                                                       const float* __restrict__ b1) {
    int gt = blockIdx.x * 256 + threadIdx.x;
    int n = gt >> 5;
    if (n >= N_NODES) return;
    int lane = gt & 31;
    int beg = __ldg(g_rowptr + n), end = __ldg(g_rowptr + n + 1);
    const uint2* q2 = (const uint2*)g_q;   // row stride 32 uint2

    float a0 = 0.f, a1 = 0.f, a2 = 0.f, a3 = 0.f;
    int j = beg;
    for (; j + 3 < end; j += 4) {
        int i0 = __ldg(g_nbrx + j);
        int i1 = __ldg(g_nbrx + j + 1);
        int i2 = __ldg(g_nbrx + j + 2);
        int i3 = __ldg(g_nbrx + j + 3);
        uint2 u0 = __ldg(q2 + i0 * 32 + lane);
        uint2 u1 = __ldg(q2 + i1 * 32 + lane);
        uint2 u2 = __ldg(q2 + i2 * 32 + lane);
        uint2 u3 = __ldg(q2 + i3 * 32 + lane);
#define ACC4(U) do { \
        float2 f0 = __half22float2(*(const __half2*)&(U).x); \
        float2 f1 = __half22float2(*(const __half2*)&(U).y); \
        a0 += f0.x; a1 += f0.y; a2 += f1.x; a3 += f1.y; } while (0)
        ACC4(u0); ACC4(u1); ACC4(u2); ACC4(u3);
    }
    for (; j < end; j++) {
        int i0 = __ldg(g_nbrx + j);
        uint2 u0 = __ldg(q2 + i0 * 32 + lane);
        ACC4(u0);
    }
#undef ACC4
    float inv = 1.0f / fmaxf((float)(end - beg), 1.0f);
    int xn = __ldg(x + n);
    float4 rv = __ldg(((const float4*)g_R) + xn * 32 + lane);
    float4 bv = __ldg(((const float4*)b1) + lane);
    float4 o;
    o.x = fmaxf(fmaf(a0, inv, rv.x + bv.x), 0.f);
    o.y = fmaxf(fmaf(a1, inv, rv.y + bv.y), 0.f);
    o.z = fmaxf(fmaf(a2, inv, rv.z + bv.z), 0.f);
    o.w = fmaxf(fmaf(a3, inv, rv.w + bv.w), 0.f);
    ((float4*)g_h1)[n * 32 + lane] = o;
}

// ---------------- dense2: [p | r] = h1 @ [W2l | W2r]  via f32x2 ----------------
// 256 thr, 64 nodes/block, smem = W packed 64KB + h1 tile packed 32KB = 96KB (2 CTA/SM).
// warp w: node group (w&3)*16, col half (w>>2)*64; lane covers cols ch+lane, ch+lane+32.
__global__ void __launch_bounds__(256) dense2_kernel(const float* __restrict__ W2l,
                                                     const float* __restrict__ W2r) {
    extern __shared__ float sm[];
    float* sW = sm;            // 16384 floats: [(k>>1)*256 + c*2 + (k&1)]
    float* sH = sm + 16384;    // 8192 floats:  [(t>>1)*256 + (k>>1)*4 + (t&1)*2 + (k&1)]
    const int tid = threadIdx.x, lane = tid & 31, wid = tid >> 5;
    const int n0 = blockIdx.x * 64;

    for (int idx = tid; idx < 16384; idx += 256) {
        int k = idx >> 7, c = idx & 127;
        float v = (c < 64) ? __ldg(W2l + k * 64 + c) : __ldg(W2r + k * 64 + (c - 64));
        sW[((k >> 1) << 8) + (c << 1) + (k & 1)] = v;
    }
    for (int idx = tid; idx < 8192; idx += 256) {
        int t = idx >> 7, k = idx & 127;
        int n = n0 + t;
        float v = (n < N_NODES) ? g_h1[n * 128 + k] : 0.f;
        sH[((t >> 1) << 8) + ((k >> 1) << 2) + ((t & 1) << 1) + (k & 1)] = v;
    }
    __syncthreads();

    const int ng = (wid & 3) * 16;      // node group base (16 nodes)
    const int ch = (wid >> 2) * 64;     // col half: 0 -> p, 64 -> r
    unsigned long long acc[16][2];
#pragma unroll
    for (int nn = 0; nn < 16; nn++) { acc[nn][0] = 0ull; acc[nn][1] = 0ull; }

    const float2* sW2 = (const float2*)sW;   // float2 idx = j2*128 + c
    const float4* sH4 = (const float4*)sH;   // float4 idx = (t>>1)*64 + j2

    for (int j2 = 0; j2 < 64; j2++) {
        float2 t0 = sW2[j2 * 128 + ch + lane];
        float2 t1 = sW2[j2 * 128 + ch + lane + 32];
        unsigned long long w0 = pk2(t0.x, t0.y);
        unsigned long long w1 = pk2(t1.x, t1.y);
#pragma unroll
        for (int p8 = 0; p8 < 8; p8++) {
            float4 hv = sH4[((ng >> 1) + p8) * 64 + j2];   // broadcast
            unsigned long long h0 = pk2(hv.x, hv.y);
            unsigned long long h1v = pk2(hv.z, hv.w);
            ffma2(acc[2 * p8][0], h0, w0);
            ffma2(acc[2 * p8][1], h0, w1);
            ffma2(acc[2 * p8 + 1][0], h1v, w0);
            ffma2(acc[2 * p8 + 1][1], h1v, w1);
        }
    }

#pragma unroll
    for (int nn = 0; nn < 16; nn++) {
        int node = n0 + ng + nn;
        if (node >= N_NODES) break;
        float2 f0 = upk2(acc[nn][0]);
        float2 f1 = upk2(acc[nn][1]);
        float r0 = f0.x + f0.y;
        float r1 = f1.x + f1.y;
        if (ch == 0) {
            g_p[node * 64 + lane] = __float2half_rn(r0);
            g_p[node * 64 + lane + 32] = __float2half_rn(r1);
        } else {
            g_r[node * 64 + lane] = r0;
            g_r[node * 64 + lane + 32] = r1;
        }
    }
}

// ---------------- gather2: agg2[n] = mean_{s in N(n)} p[s]  (p fp16) ----------------
__global__ void __launch_bounds__(256) gather2_kernel() {
    int gt = blockIdx.x * 256 + threadIdx.x;
    int n = gt >> 5;
    if (n >= N_NODES) return;
    int lane = gt & 31;
    int beg = __ldg(g_rowptr + n), end = __ldg(g_rowptr + n + 1);
    const unsigned* p2 = (const unsigned*)g_p;   // row stride 32 uints (2 halves each)

    float ax = 0.f, ay = 0.f;
    int j = beg;
    for (; j + 3 < end; j += 4) {
        int s0 = __ldg(g_nbr + j);
        int s1 = __ldg(g_nbr + j + 1);
        int s2 = __ldg(g_nbr + j + 2);
        int s3 = __ldg(g_nbr + j + 3);
        unsigned u0 = __ldg(p2 + s0 * 32 + lane);
        unsigned u1 = __ldg(p2 + s1 * 32 + lane);
        unsigned u2 = __ldg(p2 + s2 * 32 + lane);
        unsigned u3 = __ldg(p2 + s3 * 32 + lane);
#define ACC2(U) do { \
        float2 f = __half22float2(*(const __half2*)&(U)); \
        ax += f.x; ay += f.y; } while (0)
        ACC2(u0); ACC2(u1); ACC2(u2); ACC2(u3);
    }
    for (; j < end; j++) {
        int s0 = __ldg(g_nbr + j);
        unsigned u0 = __ldg(p2 + s0 * 32 + lane);
        ACC2(u0);
    }
#undef ACC2
    float inv = 1.0f / fmaxf((float)(end - beg), 1.0f);
    ((float2*)g_agg2)[n * 32 + lane] = make_float2(ax * inv, ay * inv);
}

// ---------------- final: h2 = agg2 + b2 + r ; run-length segment-max -> omax --------
__global__ void __launch_bounds__(256) final_kernel(const float* __restrict__ b2,
                                                    const int* __restrict__ batch) {
    const int tid = threadIdx.x, lane = tid & 31, warp = tid >> 5;
    const int n0 = blockIdx.x * 128 + warp * 16;
    float2 bb = ((const float2*)b2)[lane];
    const float2* ag2 = (const float2*)g_agg2;
    const float2* r2 = (const float2*)g_r;

    int curb = -1;
    float mx = 0.f, my = 0.f;
#pragma unroll
    for (int t = 0; t < 16; t++) {
        int node = n0 + t;
        if (node >= N_NODES) break;
        float2 ag = ag2[node * 32 + lane];
        float2 rr = r2[node * 32 + lane];
        float vx = ag.x + rr.x + bb.x;
        float vy = ag.y + rr.y + bb.y;
        int b = batch[node];
        if (b != curb) {
            if (curb >= 0) {
                atomicMax(&g_omax[curb * 64 + lane * 2], ordf(mx));
                atomicMax(&g_omax[curb * 64 + lane * 2 + 1], ordf(my));
            }
            curb = b; mx = vx; my = vy;
        } else {
            mx = fmaxf(mx, vx);
            my = fmaxf(my, vy);
        }
    }
    if (curb >= 0) {
        atomicMax(&g_omax[curb * 64 + lane * 2], ordf(mx));
        atomicMax(&g_omax[curb * 64 + lane * 2 + 1], ordf(my));
    }
}

// ---------------- decode ordered uints into d_out ----------------
__global__ void out_kernel(float* __restrict__ out) {
    int i = blockIdx.x * 256 + threadIdx.x;
    if (i >= NGRAPH * D0) return;
    unsigned o = g_omax[i];
    out[i] = (o & 0x80000000u) ? __uint_as_float(o & 0x7FFFFFFFu)
                               : __uint_as_float(~o);
}

// ---------------- launch ----------------
extern "C" void kernel_launch(void* const* d_in, const int* in_sizes, int n_in,
                              void* d_out, int out_size) {
    const int*   x     = (const int*)d_in[0];
    const int*   ei    = (const int*)d_in[1];     // [2, E]
    const int*   batch = (const int*)d_in[2];
    // d_in[3] = edge_attr (unused by SAGEConv)
    const float* embed = (const float*)d_in[4];
    const float* W1l   = (const float*)d_in[5];
    const float* b1    = (const float*)d_in[6];
    const float* W1r   = (const float*)d_in[7];
    const float* W2l   = (const float*)d_in[8];
    const float* b2    = (const float*)d_in[9];
    const float* W2r   = (const float*)d_in[10];
    float* out = (float*)d_out;

    const int* src = ei;
    const int* dst = ei + N_EDGES;

    cudaFuncSetAttribute(dense2_kernel,
                         cudaFuncAttributeMaxDynamicSharedMemorySize, 98304);

    init_kernel<<<128, 256>>>();
    pre_kernel<<<(VOCAB * D1 + 255) / 256, 256>>>(embed, W1l, W1r);
    hist_kernel<<<(N_EDGES + 255) / 256, 256>>>(dst);
    scan1_kernel<<<SCAN_NB, 256>>>();
    scan2_kernel<<<1, 512>>>();
    scan3_kernel<<<SCAN_NB, 256>>>();
    fill_kernel<<<(N_EDGES + 255) / 256, 256>>>(src, dst, x);
    gather1h_kernel<<<(N_NODES * 32 + 255) / 256, 256>>>(x, b1);
    dense2_kernel<<<(N_NODES + 63) / 64, 256, 98304>>>(W2l, W2r);
    gather2_kernel<<<(N_NODES * 32 + 255) / 256, 256>>>();
    final_kernel<<<(N_NODES + 127) / 128, 256>>>(b2, batch);
    out_kernel<<<(NGRAPH * D0 + 255) / 256, 256>>>(out);
}